// round 3
// baseline (speedup 1.0000x reference)
#include <cuda_runtime.h>
#include <cstdint>
#include <cstddef>

#define B_ 16384
#define T_ 64
#define H_ 64
#define R_ 300

typedef unsigned long long u64;

// ---------------- packed f32x2 helpers ----------------
__device__ __forceinline__ u64 f2pk(float a, float b) {
    u64 r; asm("mov.b64 %0, {%1, %2};" : "=l"(r) : "f"(a), "f"(b)); return r;
}
__device__ __forceinline__ void f2un(u64 v, float& a, float& b) {
    asm("mov.b64 {%0, %1}, %2;" : "=f"(a), "=f"(b) : "l"(v));
}
__device__ __forceinline__ u64 ffma2(u64 a, u64 b, u64 c) {
    u64 d; asm("fma.rn.f32x2 %0, %1, %2, %3;" : "=l"(d) : "l"(a), "l"(b), "l"(c)); return d;
}
__device__ __forceinline__ u64 fmul2(u64 a, u64 b) {
    u64 d; asm("mul.rn.f32x2 %0, %1, %2;" : "=l"(d) : "l"(a), "l"(b)); return d;
}
__device__ __forceinline__ float hadd2(u64 v) { float a, b; f2un(v, a, b); return a + b; }
__device__ __forceinline__ float frcp(float x) {
    float r; asm("rcp.approx.f32 %0, %1;" : "=f"(r) : "f"(x)); return r;
}
__device__ __forceinline__ float sigmoidf_(float x) { return frcp(1.f + __expf(-x)); }
__device__ __forceinline__ float tanhf_(float x) {
    float e = __expf(x + x);               // tanh(x) = 1 - 2/(e^{2x}+1)
    return fmaf(-2.f, frcp(e + 1.f), 1.f);
}
__device__ __forceinline__ float eluf_(float x) {
    float e = __expf(x) - 1.f;
    return x > 0.f ? x : e;
}

// ---------------- device scratch (no allocation allowed) ----------------
__device__ float g_logT[B_ * T_];
__device__ float g_logM[B_ * T_];
__device__ float g_hidT[B_ * H_];
__device__ float g_hidM[B_ * H_];
__device__ float g_rawT[B_];
__device__ float g_rawM[B_];

// ======================================================================
// Kernel 1: GRU-D scan. One batch row per thread, grid 256 x 64 threads.
// h kept in registers as 32 packed f32x2; all matvecs via fma.rn.f32x2
// against shared-memory weights (broadcast LDS.128).
// ======================================================================
#define GRU_SMEM_FLOATS (13120 + 64 * 65)
#define GRU_SMEM_BYTES  (GRU_SMEM_FLOATS * 4)

__global__ void __launch_bounds__(64) k_gru(
    const float* __restrict__ X_fa, const float* __restrict__ X_last,
    const float* __restrict__ X_mean, const float* __restrict__ X_mask,
    const float* __restrict__ X_delta,
    const float* __restrict__ W_gx, const float* __restrict__ b_gx,
    const float* __restrict__ W_gh, const float* __restrict__ b_gh,
    const float* __restrict__ W_xc, const float* __restrict__ b_xc,
    const float* __restrict__ W_hn, const float* __restrict__ W_hc,
    const float* __restrict__ W_mc,
    const float* __restrict__ W_sT, const float* __restrict__ W_sM,
    float* __restrict__ o_out, float* __restrict__ o_Xgru)
{
    extern __shared__ float sm[];
    float* sWhc = sm;              // [128][64]
    float* sWhn = sm + 8192;       // [64][64]
    float* sWgh = sm + 12288;      // 64
    float* sBgh = sm + 12352;      // 64
    float* sWxc = sm + 12416;      // 192
    float* sBxc = sm + 12608;      // 192
    float* sWmc = sm + 12800;      // 192
    float* sWsT = sm + 12992;      // 64
    float* sWsM = sm + 13056;      // 64
    float* sZ   = sm + 13120;      // [64][65]

    const int tid = threadIdx.x;
    {
        float4* dp = (float4*)sWhc; const float4* sp = (const float4*)W_hc;
        for (int i = tid; i < 2048; i += 64) dp[i] = sp[i];
        dp = (float4*)sWhn; sp = (const float4*)W_hn;
        for (int i = tid; i < 1024; i += 64) dp[i] = sp[i];
    }
    if (tid < 64) {
        sWgh[tid] = W_gh[tid]; sBgh[tid] = b_gh[tid];
        sWsT[tid] = W_sT[tid]; sWsM[tid] = W_sM[tid];
    }
    for (int i = tid; i < 192; i += 64) {
        sWxc[i] = W_xc[i]; sBxc[i] = b_xc[i]; sWmc[i] = W_mc[i];
    }
    __syncthreads();

    const float wgx = W_gx[0], bgx = b_gx[0];
    const int row = blockIdx.x * 64 + tid;

    u64 h2[32];
#pragma unroll
    for (int i = 0; i < 32; i++) h2[i] = 0ull;

    float* zsh = sZ + tid * 65;

    const float* pfa   = X_fa    + (size_t)row * T_;
    const float* plast = X_last  + (size_t)row * T_;
    const float* pmean = X_mean  + (size_t)row * T_;
    const float* pmask = X_mask  + (size_t)row * T_;
    const float* pdel  = X_delta + (size_t)row * T_;
    float* pout = o_out  + (size_t)row * (T_ * H_);
    float* pXg  = o_Xgru + (size_t)row * T_;
    float* plT  = g_logT + (size_t)row * T_;
    float* plM  = g_logM + (size_t)row * T_;

    for (int t = 0; t < T_; t++) {
        const float xi = pfa[t], xl = plast[t], xm = pmean[t];
        const float m  = pmask[t], d = pdel[t];
        const float gx = __expf(-fmaxf(fmaf(d, wgx, bgx), 0.f));
        const float om = 1.f - m;
        const float X  = m * xi + om * gx * xl + om * (1.f - gx) * xm;

        // ---- h *= exp(-relu(d*Wgh + bgh)) ----
#pragma unroll
        for (int jp = 0; jp < 32; jp++) {
            int j0 = 2 * jp;
            float a0 = __expf(-fmaxf(fmaf(d, sWgh[j0],     sBgh[j0]),     0.f));
            float a1 = __expf(-fmaxf(fmaf(d, sWgh[j0 + 1], sBgh[j0 + 1]), 0.f));
            h2[jp] = fmul2(f2pk(a0, a1), h2[jp]);
        }

        u64 rh2[32];
        // ---- Pass A: z and r gates ----
#pragma unroll
        for (int jp = 0; jp < 32; jp++) {
            const ulonglong2* Wz0 = (const ulonglong2*)(sWhc + (2 * jp) * 64);
            const ulonglong2* Wz1 = (const ulonglong2*)(sWhc + (2 * jp + 1) * 64);
            const ulonglong2* Wr0 = (const ulonglong2*)(sWhc + (64 + 2 * jp) * 64);
            const ulonglong2* Wr1 = (const ulonglong2*)(sWhc + (64 + 2 * jp + 1) * 64);
            u64 zA0 = 0, zB0 = 0, zA1 = 0, zB1 = 0;
            u64 rA0 = 0, rB0 = 0, rA1 = 0, rB1 = 0;
#pragma unroll
            for (int kk = 0; kk < 16; kk++) {
                u64 hA = h2[2 * kk], hB = h2[2 * kk + 1];
                ulonglong2 w;
                w = Wz0[kk]; zA0 = ffma2(hA, w.x, zA0); zB0 = ffma2(hB, w.y, zB0);
                w = Wz1[kk]; zA1 = ffma2(hA, w.x, zA1); zB1 = ffma2(hB, w.y, zB1);
                w = Wr0[kk]; rA0 = ffma2(hA, w.x, rA0); rB0 = ffma2(hB, w.y, rB0);
                w = Wr1[kk]; rA1 = ffma2(hA, w.x, rA1); rB1 = ffma2(hB, w.y, rB1);
            }
            int j0 = 2 * jp, j1 = j0 + 1;
            float z0 = sigmoidf_(fmaf(X, sWxc[j0], sBxc[j0]) + fmaf(m, sWmc[j0], hadd2(zA0) + hadd2(zB0)));
            float z1 = sigmoidf_(fmaf(X, sWxc[j1], sBxc[j1]) + fmaf(m, sWmc[j1], hadd2(zA1) + hadd2(zB1)));
            zsh[j0] = z0; zsh[j1] = z1;
            float r0 = sigmoidf_(fmaf(X, sWxc[64 + j0], sBxc[64 + j0]) + fmaf(m, sWmc[64 + j0], hadd2(rA0) + hadd2(rB0)));
            float r1 = sigmoidf_(fmaf(X, sWxc[64 + j1], sBxc[64 + j1]) + fmaf(m, sWmc[64 + j1], hadd2(rA1) + hadd2(rB1)));
            float h0, h1; f2un(h2[jp], h0, h1);
            rh2[jp] = f2pk(r0 * h0, r1 * h1);
        }

        // ---- Pass B: candidate + combine; h updated in place ----
        float logT = 0.f, logM = 0.f;
#pragma unroll
        for (int jp = 0; jp < 32; jp++) {
            const ulonglong2* Wn0 = (const ulonglong2*)(sWhn + (2 * jp) * 64);
            const ulonglong2* Wn1 = (const ulonglong2*)(sWhn + (2 * jp + 1) * 64);
            u64 nA0 = 0, nB0 = 0, nA1 = 0, nB1 = 0;
#pragma unroll
            for (int kk = 0; kk < 16; kk++) {
                u64 aA = rh2[2 * kk], aB = rh2[2 * kk + 1];
                ulonglong2 w;
                w = Wn0[kk]; nA0 = ffma2(aA, w.x, nA0); nB0 = ffma2(aB, w.y, nB0);
                w = Wn1[kk]; nA1 = ffma2(aA, w.x, nA1); nB1 = ffma2(aB, w.y, nB1);
            }
            int j0 = 2 * jp, j1 = j0 + 1;
            float pre0 = fmaf(X, sWxc[128 + j0], sBxc[128 + j0]) + fmaf(m, sWmc[128 + j0], hadd2(nA0) + hadd2(nB0));
            float pre1 = fmaf(X, sWxc[128 + j1], sBxc[128 + j1]) + fmaf(m, sWmc[128 + j1], hadd2(nA1) + hadd2(nB1));
            float ht0 = tanhf_(pre0), ht1 = tanhf_(pre1);
            float h0, h1; f2un(h2[jp], h0, h1);
            float z0 = zsh[j0], z1 = zsh[j1];
            h0 = fmaf(z0, ht0 - h0, h0);
            h1 = fmaf(z1, ht1 - h1, h1);
            h2[jp] = f2pk(h0, h1);
            logT = fmaf(h0, sWsT[j0], fmaf(h1, sWsT[j1], logT));
            logM = fmaf(h0, sWsM[j0], fmaf(h1, sWsM[j1], logM));
            float2 st; st.x = h0; st.y = h1;
            *(float2*)(pout + t * 64 + j0) = st;
        }
        plT[t] = logT; plM[t] = logM; pXg[t] = X;
    }
}

// ======================================================================
// Kernel 2: softmax over time (both heads) + attention pooling.
// One block per batch row; warp0 computes T-softmax, warp1 M-softmax,
// then 64 threads (h index) accumulate both pooled vectors in one pass.
// ======================================================================
__global__ void __launch_bounds__(64) k_attn(const float* __restrict__ out)
{
    __shared__ float swT[64], swM[64];
    const int b = blockIdx.x;
    const int tid = threadIdx.x;
    const int wid = tid >> 5, lane = tid & 31;

    const float* lg = (wid == 0) ? g_logT : g_logM;
    float l0 = lg[(size_t)b * 64 + lane];
    float l1 = lg[(size_t)b * 64 + 32 + lane];
    float mx = fmaxf(l0, l1);
#pragma unroll
    for (int o = 16; o; o >>= 1) mx = fmaxf(mx, __shfl_xor_sync(0xffffffffu, mx, o));
    float e0 = __expf(l0 - mx), e1 = __expf(l1 - mx);
    float s = e0 + e1;
#pragma unroll
    for (int o = 16; o; o >>= 1) s += __shfl_xor_sync(0xffffffffu, s, o);
    float inv = frcp(s);
    float* sw = (wid == 0) ? swT : swM;
    sw[lane] = e0 * inv;
    sw[lane + 32] = e1 * inv;
    __syncthreads();

    float aT = 0.f, aM = 0.f;
    const float* po = out + (size_t)b * 4096 + tid;
#pragma unroll 8
    for (int t = 0; t < 64; t++) {
        float v = po[(size_t)t * 64];
        aT = fmaf(swT[t], v, aT);
        aM = fmaf(swM[t], v, aM);
    }
    g_hidT[(size_t)b * 64 + tid] = aT;
    g_hidM[(size_t)b * 64 + tid] = aM;
}

// ======================================================================
// Kernel 3: the two 64 -> 300 -> 300 -> 1 ELU MLPs.
// One thread per batch row, 128 rows/block, act1 staged in shared
// (row stride 302 floats = odd 8B-unit stride -> conflict-free LDS.64).
// Layer2 uses J=8 output blocking: 1 act load feeds 8 ffma2; W2 rows
// read as broadcast LDG.128 (L2-resident). grid = (128, 2 heads).
// ======================================================================
#define MLP_PAD  302
#define MLP_SMEM (128 * MLP_PAD * 4)

__global__ void __launch_bounds__(128) k_mlp(
    const float* __restrict__ Wt1, const float* __restrict__ bt1,
    const float* __restrict__ Wt2, const float* __restrict__ bt2,
    const float* __restrict__ Wt3, const float* __restrict__ bt3,
    const float* __restrict__ Wm1, const float* __restrict__ bm1,
    const float* __restrict__ Wm2, const float* __restrict__ bm2,
    const float* __restrict__ Wm3, const float* __restrict__ bm3)
{
    extern __shared__ float sact[];
    const int head = blockIdx.y;
    const float* hid = head ? g_hidM : g_hidT;
    const float* W1 = head ? Wm1 : Wt1;  const float* b1 = head ? bm1 : bt1;
    const float* W2 = head ? Wm2 : Wt2;  const float* b2 = head ? bm2 : bt2;
    const float* W3 = head ? Wm3 : Wt3;  const float* b3 = head ? bm3 : bt3;
    float* rawOut = head ? g_rawM : g_rawT;

    const int tid = threadIdx.x;
    const int row = blockIdx.x * 128 + tid;

    // layer 1: 64 -> 300
    u64 h2[32];
    {
        const ulonglong2* hp = (const ulonglong2*)(hid + (size_t)row * 64);
#pragma unroll
        for (int i = 0; i < 16; i++) { ulonglong2 v = hp[i]; h2[2 * i] = v.x; h2[2 * i + 1] = v.y; }
    }
    float* arow = sact + tid * MLP_PAD;
    for (int j = 0; j < 300; j++) {
        const ulonglong2* wp = (const ulonglong2*)(W1 + j * 64);
        u64 aA = 0, aB = 0;
#pragma unroll
        for (int kk = 0; kk < 16; kk++) {
            ulonglong2 w = wp[kk];
            aA = ffma2(h2[2 * kk], w.x, aA);
            aB = ffma2(h2[2 * kk + 1], w.y, aB);
        }
        arow[j] = eluf_(hadd2(aA) + hadd2(aB) + b1[j]);
    }
    // no sync needed: each thread reads only its own act1 row

    // layer 2 + 3: 300 -> 300 (elu) -> dot with W3
    float raw = 0.f;
    const u64* ap = (const u64*)arow;
    for (int jt = 0; jt < 38; jt++) {
        const int j0 = jt * 8;
        const ulonglong2* wrow[8];
#pragma unroll
        for (int u = 0; u < 8; u++) {
            int jr = j0 + u; if (jr > 299) jr = 299;
            wrow[u] = (const ulonglong2*)(W2 + (size_t)jr * 300);
        }
        u64 aA[8], aB[8];
#pragma unroll
        for (int u = 0; u < 8; u++) { aA[u] = 0; aB[u] = 0; }
        for (int kk = 0; kk < 75; kk++) {
            u64 a0 = ap[2 * kk], a1 = ap[2 * kk + 1];
#pragma unroll
            for (int u = 0; u < 8; u++) {
                ulonglong2 w = wrow[u][kk];
                aA[u] = ffma2(a0, w.x, aA[u]);
                aB[u] = ffma2(a1, w.y, aB[u]);
            }
        }
#pragma unroll
        for (int u = 0; u < 8; u++) {
            int jr = j0 + u;
            if (jr < 300) {
                float s = hadd2(aA[u]) + hadd2(aB[u]) + b2[jr];
                raw = fmaf(eluf_(s), W3[jr], raw);
            }
        }
    }
    rawOut[row] = raw + b3[0];
}

// ======================================================================
// Kernel 4: heads -> T10/M0 -> closed-form X_out
// ======================================================================
__global__ void __launch_bounds__(256) k_final(
    const float* __restrict__ fa, const float* __restrict__ TR,
    float* __restrict__ o_Xout, float* __restrict__ o_T10, float* __restrict__ o_M0)
{
    const int b = blockIdx.x * 256 + threadIdx.x;
    const float T10 = 0.2f + sigmoidf_(g_rawT[b]) * 4.8f;
    const float M0v = 0.1f + sigmoidf_(g_rawM[b]) * 19.9f;
    o_T10[b] = T10;
    o_M0[b]  = M0v;
    const float e = __expf(-TR[b] / T10);
    const float one_m_e = 1.f - e;
#pragma unroll 4
    for (int t = 0; t < 64; t++) {
        float f = fa[(size_t)b * 64 + t];
        float num = one_m_e * __sinf(f);
        float den = 1.f - __cosf(f) * e;
        o_Xout[(size_t)b * 64 + t] = num / den * M0v;
    }
}

// ======================================================================
extern "C" void kernel_launch(void* const* d_in, const int* in_sizes, int n_in,
                              void* d_out, int out_size)
{
    const float* X_fa    = (const float*)d_in[0];
    const float* X_last  = (const float*)d_in[1];
    const float* X_mean  = (const float*)d_in[2];
    const float* X_mask  = (const float*)d_in[3];
    const float* X_delta = (const float*)d_in[4];
    const float* fa_vals = (const float*)d_in[5];
    const float* TR_vals = (const float*)d_in[6];
    const float* W_gx = (const float*)d_in[7];
    const float* b_gx = (const float*)d_in[8];
    const float* W_gh = (const float*)d_in[9];
    const float* b_gh = (const float*)d_in[10];
    const float* W_xc = (const float*)d_in[11];
    const float* b_xc = (const float*)d_in[12];
    const float* W_hn = (const float*)d_in[13];
    const float* W_hc = (const float*)d_in[14];
    const float* W_mc = (const float*)d_in[15];
    const float* W_sT = (const float*)d_in[16];
    const float* W_sM = (const float*)d_in[17];
    const float* Wt1 = (const float*)d_in[18];
    const float* bt1 = (const float*)d_in[19];
    const float* Wt2 = (const float*)d_in[20];
    const float* bt2 = (const float*)d_in[21];
    const float* Wt3 = (const float*)d_in[22];
    const float* bt3 = (const float*)d_in[23];
    const float* Wm1 = (const float*)d_in[24];
    const float* bm1 = (const float*)d_in[25];
    const float* Wm2 = (const float*)d_in[26];
    const float* bm2 = (const float*)d_in[27];
    const float* Wm3 = (const float*)d_in[28];
    const float* bm3 = (const float*)d_in[29];

    float* outp = (float*)d_out;
    // outputs concatenated in reference return order
    float* o_Xout = outp;                       // [B,T]   1,048,576
    float* o_T10  = outp + 1048576;             // [B,1]      16,384
    float* o_M0   = outp + 1064960;             // [B,1]      16,384
    float* o_out  = outp + 1081344;             // [B,T,H] 67,108,864
    float* o_Xgru = outp + 68190208;            // [B,T]   1,048,576

    cudaFuncSetAttribute(k_gru, cudaFuncAttributeMaxDynamicSharedMemorySize, GRU_SMEM_BYTES);
    cudaFuncSetAttribute(k_mlp, cudaFuncAttributeMaxDynamicSharedMemorySize, MLP_SMEM);

    k_gru<<<B_ / 64, 64, GRU_SMEM_BYTES>>>(
        X_fa, X_last, X_mean, X_mask, X_delta,
        W_gx, b_gx, W_gh, b_gh, W_xc, b_xc, W_hn, W_hc, W_mc,
        W_sT, W_sM, o_out, o_Xgru);

    k_attn<<<B_, 64>>>(o_out);

    dim3 mgrid(B_ / 128, 2);
    k_mlp<<<mgrid, 128, MLP_SMEM>>>(Wt1, bt1, Wt2, bt2, Wt3, bt3,
                                    Wm1, bm1, Wm2, bm2, Wm3, bm3);

    k_final<<<B_ / 256, 256>>>(fa_vals, TR_vals, o_Xout, o_T10, o_M0);
}

// round 5
// speedup vs baseline: 1.7185x; 1.7185x over previous
#include <cuda_runtime.h>
#include <cstdint>
#include <cstddef>

#define B_ 16384
#define T_ 64
#define H_ 64
#define R_ 300

typedef unsigned long long u64;

// ---------------- packed f32x2 helpers ----------------
__device__ __forceinline__ u64 f2pk(float a, float b) {
    u64 r; asm("mov.b64 %0, {%1, %2};" : "=l"(r) : "f"(a), "f"(b)); return r;
}
__device__ __forceinline__ void f2un(u64 v, float& a, float& b) {
    asm("mov.b64 {%0, %1}, %2;" : "=f"(a), "=f"(b) : "l"(v));
}
__device__ __forceinline__ u64 ffma2(u64 a, u64 b, u64 c) {
    u64 d; asm("fma.rn.f32x2 %0, %1, %2, %3;" : "=l"(d) : "l"(a), "l"(b), "l"(c)); return d;
}
__device__ __forceinline__ float hadd2(u64 v) { float a, b; f2un(v, a, b); return a + b; }
__device__ __forceinline__ float frcp(float x) {
    float r; asm("rcp.approx.f32 %0, %1;" : "=f"(r) : "f"(x)); return r;
}
__device__ __forceinline__ float sigmoidf_(float x) { return frcp(1.f + __expf(-x)); }
__device__ __forceinline__ float tanhf_(float x) {
    float e = __expf(x + x);               // tanh(x) = 1 - 2/(e^{2x}+1)
    return fmaf(-2.f, frcp(e + 1.f), 1.f);
}
__device__ __forceinline__ float eluf_(float x) {
    float e = __expf(x) - 1.f;
    return x > 0.f ? x : e;
}

// ---------------- device scratch ----------------
__device__ float g_hidT[B_ * H_];
__device__ float g_hidM[B_ * H_];
__device__ float g_rawT[B_];
__device__ float g_rawM[B_];

// ======================================================================
// Kernel 1: GRU-D scan, GEMM-structured.
// Block = 128 batch rows for the whole T loop. 512 threads.
// Thread tile: 4 rows x 4 hidden-j. h / rh tiles in shared [row][k],
// weights transposed in shared [k][j]. All matvecs via fma.rn.f32x2.
// Barriers per step: (A) inputs staged, (B) decay done, (C) rh ready,
// (D) end-of-step: combine's sX/sM reads complete before next staging.
// ======================================================================
#define S_H 68
#define GRU_SMEM_FLOATS (8192 + 4096 + 128 * S_H + 128 * S_H + 64 + 64 + 192 + 192 + 192 + 128 + 128 + 128)
#define GRU_SMEM_BYTES  (GRU_SMEM_FLOATS * 4)

__global__ void __launch_bounds__(512) k_gru(
    const float* __restrict__ X_fa, const float* __restrict__ X_last,
    const float* __restrict__ X_mean, const float* __restrict__ X_mask,
    const float* __restrict__ X_delta,
    const float* __restrict__ W_gx, const float* __restrict__ b_gx,
    const float* __restrict__ W_gh, const float* __restrict__ b_gh,
    const float* __restrict__ W_xc, const float* __restrict__ b_xc,
    const float* __restrict__ W_hn, const float* __restrict__ W_hc,
    const float* __restrict__ W_mc,
    float* __restrict__ o_out, float* __restrict__ o_Xgru)
{
    extern __shared__ float sm[];
    float* sWzr = sm;                    // [64][128] : W_hc transposed (z | r)
    float* sWn  = sWzr + 8192;           // [64][64]  : W_hn transposed
    float* sH   = sWn + 4096;            // [128][S_H]
    float* sRH  = sH + 128 * S_H;        // [128][S_H]
    float* sWgh = sRH + 128 * S_H;       // 64
    float* sBgh = sWgh + 64;             // 64
    float* sWxc = sBgh + 64;             // 192
    float* sBxc = sWxc + 192;            // 192
    float* sWmc = sBxc + 192;            // 192
    float* sX   = sWmc + 192;            // 128
    float* sM   = sX + 128;              // 128
    float* sD   = sM + 128;              // 128

    const int tid = threadIdx.x;
    for (int i = tid; i < 8192; i += 512) sWzr[(i & 63) * 128 + (i >> 6)] = W_hc[i];
    for (int i = tid; i < 4096; i += 512) sWn[(i & 63) * 64 + (i >> 6)] = W_hn[i];
    if (tid < 64) { sWgh[tid] = W_gh[tid]; sBgh[tid] = b_gh[tid]; }
    if (tid < 192) { sWxc[tid] = W_xc[tid]; sBxc[tid] = b_xc[tid]; sWmc[tid] = W_mc[tid]; }
    for (int i = tid; i < 128 * S_H; i += 512) sH[i] = 0.f;

    const int jt = tid & 15;
    const int rt = tid >> 4;
    const int j0 = jt * 4;
    const int r0 = rt * 4;
    const int rowbase = blockIdx.x * 128;
    const float wgx = W_gx[0], bgx0 = b_gx[0];

    float pf_xi = 0.f, pf_xl = 0.f, pf_xm = 0.f, pf_m = 0.f, pf_d = 0.f;
    const int myrow = rowbase + tid;
    if (tid < 128) {
        pf_xi = X_fa   [(size_t)myrow * T_];
        pf_xl = X_last [(size_t)myrow * T_];
        pf_xm = X_mean [(size_t)myrow * T_];
        pf_m  = X_mask [(size_t)myrow * T_];
        pf_d  = X_delta[(size_t)myrow * T_];
    }
    __syncthreads();

    for (int t = 0; t < T_; t++) {
        // ---- stage inputs for this step; prefetch t+1 ----
        if (tid < 128) {
            const float d = pf_d, m = pf_m;
            const float gx = __expf(-fmaxf(fmaf(d, wgx, bgx0), 0.f));
            const float om = 1.f - m;
            const float Xv = m * pf_xi + om * gx * pf_xl + om * (1.f - gx) * pf_xm;
            sX[tid] = Xv; sM[tid] = m; sD[tid] = d;
            o_Xgru[(size_t)myrow * T_ + t] = Xv;
            if (t + 1 < T_) {
                pf_xi = X_fa   [(size_t)myrow * T_ + t + 1];
                pf_xl = X_last [(size_t)myrow * T_ + t + 1];
                pf_xm = X_mean [(size_t)myrow * T_ + t + 1];
                pf_m  = X_mask [(size_t)myrow * T_ + t + 1];
                pf_d  = X_delta[(size_t)myrow * T_ + t + 1];
            }
        }
        __syncthreads();   // (A) sX/sM/sD ready

        // ---- decay: h(r, j) *= exp(-relu(d_r * Wgh_j + bgh_j)) ----
#pragma unroll
        for (int rr = 0; rr < 4; rr++) {
            const int r = r0 + rr;
            const float d = sD[r];
            float g0 = __expf(-fmaxf(fmaf(d, sWgh[j0 + 0], sBgh[j0 + 0]), 0.f));
            float g1 = __expf(-fmaxf(fmaf(d, sWgh[j0 + 1], sBgh[j0 + 1]), 0.f));
            float g2 = __expf(-fmaxf(fmaf(d, sWgh[j0 + 2], sBgh[j0 + 2]), 0.f));
            float g3 = __expf(-fmaxf(fmaf(d, sWgh[j0 + 3], sBgh[j0 + 3]), 0.f));
            float4 h4 = *(float4*)(sH + r * S_H + j0);
            h4.x *= g0; h4.y *= g1; h4.z *= g2; h4.w *= g3;
            *(float4*)(sH + r * S_H + j0) = h4;
        }
        __syncthreads();   // (B) all decays visible

        // ---- GEMM1: z, r gates ----
        u64 az[4][2], ar[4][2];
#pragma unroll
        for (int rr = 0; rr < 4; rr++) { az[rr][0] = az[rr][1] = 0ull; ar[rr][0] = ar[rr][1] = 0ull; }
#pragma unroll 16
        for (int k = 0; k < 64; k++) {
            const float* hp = sH + r0 * S_H + k;
            u64 hs0 = f2pk(hp[0],        hp[0]);
            u64 hs1 = f2pk(hp[S_H],      hp[S_H]);
            u64 hs2 = f2pk(hp[2 * S_H],  hp[2 * S_H]);
            u64 hs3 = f2pk(hp[3 * S_H],  hp[3 * S_H]);
            const ulonglong2 wz = *(const ulonglong2*)(sWzr + k * 128 + j0);
            const ulonglong2 wr = *(const ulonglong2*)(sWzr + k * 128 + 64 + j0);
            az[0][0] = ffma2(hs0, wz.x, az[0][0]); az[0][1] = ffma2(hs0, wz.y, az[0][1]);
            az[1][0] = ffma2(hs1, wz.x, az[1][0]); az[1][1] = ffma2(hs1, wz.y, az[1][1]);
            az[2][0] = ffma2(hs2, wz.x, az[2][0]); az[2][1] = ffma2(hs2, wz.y, az[2][1]);
            az[3][0] = ffma2(hs3, wz.x, az[3][0]); az[3][1] = ffma2(hs3, wz.y, az[3][1]);
            ar[0][0] = ffma2(hs0, wr.x, ar[0][0]); ar[0][1] = ffma2(hs0, wr.y, ar[0][1]);
            ar[1][0] = ffma2(hs1, wr.x, ar[1][0]); ar[1][1] = ffma2(hs1, wr.y, ar[1][1]);
            ar[2][0] = ffma2(hs2, wr.x, ar[2][0]); ar[2][1] = ffma2(hs2, wr.y, ar[2][1]);
            ar[3][0] = ffma2(hs3, wr.x, ar[3][0]); ar[3][1] = ffma2(hs3, wr.y, ar[3][1]);
        }

        // ---- gates + rh ----
        float zreg[4][4];
#pragma unroll
        for (int rr = 0; rr < 4; rr++) {
            const int r = r0 + rr;
            const float Xv = sX[r], mv = sM[r];
            float a0, a1, a2, a3, b0v, b1v, b2v, b3v;
            f2un(az[rr][0], a0, a1); f2un(az[rr][1], a2, a3);
            f2un(ar[rr][0], b0v, b1v); f2un(ar[rr][1], b2v, b3v);
            float z0 = sigmoidf_(a0 + fmaf(Xv, sWxc[j0 + 0], sBxc[j0 + 0]) + mv * sWmc[j0 + 0]);
            float z1 = sigmoidf_(a1 + fmaf(Xv, sWxc[j0 + 1], sBxc[j0 + 1]) + mv * sWmc[j0 + 1]);
            float z2 = sigmoidf_(a2 + fmaf(Xv, sWxc[j0 + 2], sBxc[j0 + 2]) + mv * sWmc[j0 + 2]);
            float z3 = sigmoidf_(a3 + fmaf(Xv, sWxc[j0 + 3], sBxc[j0 + 3]) + mv * sWmc[j0 + 3]);
            float r0g = sigmoidf_(b0v + fmaf(Xv, sWxc[64 + j0 + 0], sBxc[64 + j0 + 0]) + mv * sWmc[64 + j0 + 0]);
            float r1g = sigmoidf_(b1v + fmaf(Xv, sWxc[64 + j0 + 1], sBxc[64 + j0 + 1]) + mv * sWmc[64 + j0 + 1]);
            float r2g = sigmoidf_(b2v + fmaf(Xv, sWxc[64 + j0 + 2], sBxc[64 + j0 + 2]) + mv * sWmc[64 + j0 + 2]);
            float r3g = sigmoidf_(b3v + fmaf(Xv, sWxc[64 + j0 + 3], sBxc[64 + j0 + 3]) + mv * sWmc[64 + j0 + 3]);
            zreg[rr][0] = z0; zreg[rr][1] = z1; zreg[rr][2] = z2; zreg[rr][3] = z3;
            float4 h4 = *(float4*)(sH + r * S_H + j0);
            float4 rh4;
            rh4.x = r0g * h4.x; rh4.y = r1g * h4.y; rh4.z = r2g * h4.z; rh4.w = r3g * h4.w;
            *(float4*)(sRH + r * S_H + j0) = rh4;
        }
        __syncthreads();   // (C) sRH ready everywhere

        // ---- GEMM2: candidate ----
        u64 an[4][2];
#pragma unroll
        for (int rr = 0; rr < 4; rr++) { an[rr][0] = an[rr][1] = 0ull; }
#pragma unroll 16
        for (int k = 0; k < 64; k++) {
            const float* rp = sRH + r0 * S_H + k;
            u64 rs0 = f2pk(rp[0],       rp[0]);
            u64 rs1 = f2pk(rp[S_H],     rp[S_H]);
            u64 rs2 = f2pk(rp[2 * S_H], rp[2 * S_H]);
            u64 rs3 = f2pk(rp[3 * S_H], rp[3 * S_H]);
            const ulonglong2 wn = *(const ulonglong2*)(sWn + k * 64 + j0);
            an[0][0] = ffma2(rs0, wn.x, an[0][0]); an[0][1] = ffma2(rs0, wn.y, an[0][1]);
            an[1][0] = ffma2(rs1, wn.x, an[1][0]); an[1][1] = ffma2(rs1, wn.y, an[1][1]);
            an[2][0] = ffma2(rs2, wn.x, an[2][0]); an[2][1] = ffma2(rs2, wn.y, an[2][1]);
            an[3][0] = ffma2(rs3, wn.x, an[3][0]); an[3][1] = ffma2(rs3, wn.y, an[3][1]);
        }

        // ---- combine + store ----
#pragma unroll
        for (int rr = 0; rr < 4; rr++) {
            const int r = r0 + rr;
            const float Xv = sX[r], mv = sM[r];
            float n0, n1, n2, n3;
            f2un(an[rr][0], n0, n1); f2un(an[rr][1], n2, n3);
            float p0 = n0 + fmaf(Xv, sWxc[128 + j0 + 0], sBxc[128 + j0 + 0]) + mv * sWmc[128 + j0 + 0];
            float p1 = n1 + fmaf(Xv, sWxc[128 + j0 + 1], sBxc[128 + j0 + 1]) + mv * sWmc[128 + j0 + 1];
            float p2 = n2 + fmaf(Xv, sWxc[128 + j0 + 2], sBxc[128 + j0 + 2]) + mv * sWmc[128 + j0 + 2];
            float p3 = n3 + fmaf(Xv, sWxc[128 + j0 + 3], sBxc[128 + j0 + 3]) + mv * sWmc[128 + j0 + 3];
            float t0 = tanhf_(p0), t1 = tanhf_(p1), t2 = tanhf_(p2), t3 = tanhf_(p3);
            float4 h4 = *(float4*)(sH + r * S_H + j0);
            h4.x = fmaf(zreg[rr][0], t0 - h4.x, h4.x);
            h4.y = fmaf(zreg[rr][1], t1 - h4.y, h4.y);
            h4.z = fmaf(zreg[rr][2], t2 - h4.z, h4.z);
            h4.w = fmaf(zreg[rr][3], t3 - h4.w, h4.w);
            *(float4*)(sH + r * S_H + j0) = h4;
            *(float4*)(o_out + (((size_t)(rowbase + r)) * T_ + t) * H_ + j0) = h4;
        }
        __syncthreads();   // (D) combine's sX/sM reads done before next staging
    }
}

// ======================================================================
// Kernel 2: logits + time-softmax (both heads) + attention pooling.
// ======================================================================
__global__ void __launch_bounds__(64) k_attn(
    const float* __restrict__ out,
    const float* __restrict__ W_sT, const float* __restrict__ W_sM)
{
    __shared__ float sWt[64], sWm[64], slT[64], slM[64], swT[64], swM[64];
    const int b = blockIdx.x;
    const int tid = threadIdx.x;
    sWt[tid] = W_sT[tid]; sWm[tid] = W_sM[tid];
    __syncthreads();

    const float4* p = (const float4*)(out + (size_t)b * 4096 + (size_t)tid * 64);
    float lT = 0.f, lM = 0.f;
#pragma unroll
    for (int i = 0; i < 16; i++) {
        float4 v = p[i];
        lT += v.x * sWt[4 * i] + v.y * sWt[4 * i + 1] + v.z * sWt[4 * i + 2] + v.w * sWt[4 * i + 3];
        lM += v.x * sWm[4 * i] + v.y * sWm[4 * i + 1] + v.z * sWm[4 * i + 2] + v.w * sWm[4 * i + 3];
    }
    slT[tid] = lT; slM[tid] = lM;
    __syncthreads();

    const int wid = tid >> 5, lane = tid & 31;
    const float* lg = wid ? slM : slT;
    float l0 = lg[lane], l1 = lg[lane + 32];
    float mx = fmaxf(l0, l1);
#pragma unroll
    for (int o = 16; o; o >>= 1) mx = fmaxf(mx, __shfl_xor_sync(0xffffffffu, mx, o));
    float e0 = __expf(l0 - mx), e1 = __expf(l1 - mx);
    float s = e0 + e1;
#pragma unroll
    for (int o = 16; o; o >>= 1) s += __shfl_xor_sync(0xffffffffu, s, o);
    float inv = frcp(s);
    float* sw = wid ? swM : swT;
    sw[lane] = e0 * inv; sw[lane + 32] = e1 * inv;
    __syncthreads();

    float aT = 0.f, aM = 0.f;
    const float* po = out + (size_t)b * 4096 + tid;
#pragma unroll 8
    for (int t = 0; t < 64; t++) {
        float v = po[(size_t)t * 64];
        aT = fmaf(swT[t], v, aT);
        aM = fmaf(swM[t], v, aM);
    }
    g_hidT[(size_t)b * 64 + tid] = aT;
    g_hidM[(size_t)b * 64 + tid] = aM;
}

// ======================================================================
// Kernel 3: two 64->300->300->1 ELU MLPs.
// ======================================================================
#define MLP_PAD  302
#define MLP_SMEM (128 * MLP_PAD * 4)

__global__ void __launch_bounds__(128) k_mlp(
    const float* __restrict__ Wt1, const float* __restrict__ bt1,
    const float* __restrict__ Wt2, const float* __restrict__ bt2,
    const float* __restrict__ Wt3, const float* __restrict__ bt3,
    const float* __restrict__ Wm1, const float* __restrict__ bm1,
    const float* __restrict__ Wm2, const float* __restrict__ bm2,
    const float* __restrict__ Wm3, const float* __restrict__ bm3)
{
    extern __shared__ float sact[];
    const int head = blockIdx.y;
    const float* hid = head ? g_hidM : g_hidT;
    const float* W1 = head ? Wm1 : Wt1;  const float* b1 = head ? bm1 : bt1;
    const float* W2 = head ? Wm2 : Wt2;  const float* b2 = head ? bm2 : bt2;
    const float* W3 = head ? Wm3 : Wt3;  const float* b3 = head ? bm3 : bt3;
    float* rawOut = head ? g_rawM : g_rawT;

    const int tid = threadIdx.x;
    const int row = blockIdx.x * 128 + tid;

    u64 h2[32];
    {
        const ulonglong2* hp = (const ulonglong2*)(hid + (size_t)row * 64);
#pragma unroll
        for (int i = 0; i < 16; i++) { ulonglong2 v = hp[i]; h2[2 * i] = v.x; h2[2 * i + 1] = v.y; }
    }
    float* arow = sact + tid * MLP_PAD;
    for (int j = 0; j < 300; j++) {
        const ulonglong2* wp = (const ulonglong2*)(W1 + j * 64);
        u64 aA = 0, aB = 0;
#pragma unroll
        for (int kk = 0; kk < 16; kk++) {
            ulonglong2 w = wp[kk];
            aA = ffma2(h2[2 * kk], w.x, aA);
            aB = ffma2(h2[2 * kk + 1], w.y, aB);
        }
        arow[j] = eluf_(hadd2(aA) + hadd2(aB) + b1[j]);
    }

    float raw = 0.f;
    const u64* ap = (const u64*)arow;
    for (int jt = 0; jt < 38; jt++) {
        const int j0 = jt * 8;
        const ulonglong2* wrow[8];
#pragma unroll
        for (int u = 0; u < 8; u++) {
            int jr = j0 + u; if (jr > 299) jr = 299;
            wrow[u] = (const ulonglong2*)(W2 + (size_t)jr * 300);
        }
        u64 aA[8], aB[8];
#pragma unroll
        for (int u = 0; u < 8; u++) { aA[u] = 0; aB[u] = 0; }
        for (int kk = 0; kk < 75; kk++) {
            u64 a0 = ap[2 * kk], a1 = ap[2 * kk + 1];
#pragma unroll
            for (int u = 0; u < 8; u++) {
                ulonglong2 w = wrow[u][kk];
                aA[u] = ffma2(a0, w.x, aA[u]);
                aB[u] = ffma2(a1, w.y, aB[u]);
            }
        }
#pragma unroll
        for (int u = 0; u < 8; u++) {
            int jr = j0 + u;
            if (jr < 300) {
                float s = hadd2(aA[u]) + hadd2(aB[u]) + b2[jr];
                raw = fmaf(eluf_(s), W3[jr], raw);
            }
        }
    }
    rawOut[row] = raw + b3[0];
}

// ======================================================================
// Kernel 4: heads -> T10/M0 -> closed-form X_out
// ======================================================================
__global__ void __launch_bounds__(256) k_final(
    const float* __restrict__ fa, const float* __restrict__ TR,
    float* __restrict__ o_Xout, float* __restrict__ o_T10, float* __restrict__ o_M0)
{
    const int b = blockIdx.x * 256 + threadIdx.x;
    const float T10 = 0.2f + sigmoidf_(g_rawT[b]) * 4.8f;
    const float M0v = 0.1f + sigmoidf_(g_rawM[b]) * 19.9f;
    o_T10[b] = T10;
    o_M0[b]  = M0v;
    const float e = __expf(-TR[b] / T10);
    const float one_m_e = 1.f - e;
#pragma unroll 4
    for (int t = 0; t < 64; t++) {
        float f = fa[(size_t)b * 64 + t];
        float num = one_m_e * __sinf(f);
        float den = 1.f - __cosf(f) * e;
        o_Xout[(size_t)b * 64 + t] = num / den * M0v;
    }
}

// ======================================================================
extern "C" void kernel_launch(void* const* d_in, const int* in_sizes, int n_in,
                              void* d_out, int out_size)
{
    const float* X_fa    = (const float*)d_in[0];
    const float* X_last  = (const float*)d_in[1];
    const float* X_mean  = (const float*)d_in[2];
    const float* X_mask  = (const float*)d_in[3];
    const float* X_delta = (const float*)d_in[4];
    const float* fa_vals = (const float*)d_in[5];
    const float* TR_vals = (const float*)d_in[6];
    const float* W_gx = (const float*)d_in[7];
    const float* b_gx = (const float*)d_in[8];
    const float* W_gh = (const float*)d_in[9];
    const float* b_gh = (const float*)d_in[10];
    const float* W_xc = (const float*)d_in[11];
    const float* b_xc = (const float*)d_in[12];
    const float* W_hn = (const float*)d_in[13];
    const float* W_hc = (const float*)d_in[14];
    const float* W_mc = (const float*)d_in[15];
    const float* W_sT = (const float*)d_in[16];
    const float* W_sM = (const float*)d_in[17];
    const float* Wt1 = (const float*)d_in[18];
    const float* bt1 = (const float*)d_in[19];
    const float* Wt2 = (const float*)d_in[20];
    const float* bt2 = (const float*)d_in[21];
    const float* Wt3 = (const float*)d_in[22];
    const float* bt3 = (const float*)d_in[23];
    const float* Wm1 = (const float*)d_in[24];
    const float* bm1 = (const float*)d_in[25];
    const float* Wm2 = (const float*)d_in[26];
    const float* bm2 = (const float*)d_in[27];
    const float* Wm3 = (const float*)d_in[28];
    const float* bm3 = (const float*)d_in[29];

    float* outp = (float*)d_out;
    float* o_Xout = outp;                       // [B,T]
    float* o_T10  = outp + 1048576;             // [B,1]
    float* o_M0   = outp + 1064960;             // [B,1]
    float* o_out  = outp + 1081344;             // [B,T,H]
    float* o_Xgru = outp + 68190208;            // [B,T]

    cudaFuncSetAttribute(k_gru, cudaFuncAttributeMaxDynamicSharedMemorySize, GRU_SMEM_BYTES);
    cudaFuncSetAttribute(k_mlp, cudaFuncAttributeMaxDynamicSharedMemorySize, MLP_SMEM);

    k_gru<<<B_ / 128, 512, GRU_SMEM_BYTES>>>(
        X_fa, X_last, X_mean, X_mask, X_delta,
        W_gx, b_gx, W_gh, b_gh, W_xc, b_xc, W_hn, W_hc, W_mc,
        o_out, o_Xgru);

    k_attn<<<B_, 64>>>(o_out, W_sT, W_sM);

    dim3 mgrid(B_ / 128, 2);
    k_mlp<<<mgrid, 128, MLP_SMEM>>>(Wt1, bt1, Wt2, bt2, Wt3, bt3,
                                    Wm1, bm1, Wm2, bm2, Wm3, bm3);

    k_final<<<B_ / 256, 256>>>(fa_vals, TR_vals, o_Xout, o_T10, o_M0);
}